// round 15
// baseline (speedup 1.0000x reference)
#include <cuda_runtime.h>
#include <cuda_fp16.h>
#include <cstdint>
#include <math.h>

#define N_ 4096
#define F_ 512
#define TM 128
#define TNJ 128
#define BK 64
#define NCH (F_ / BK)            // 8 k-chunks
#define TILE_BYTES 16384         // 128 rows x 128B
#define STAGE_BYTES (2 * TILE_BYTES)   // 32KB
#define SMEM_TOTAL (3 * STAGE_BYTES)   // 98304, 2 CTAs/SM
#define PMAX 512                 // slots per row (max class size ~306)

// ---------------- scratch ----------------
__device__ __align__(16) __half g_ah[(size_t)N_ * F_];   // permuted rows
__device__ __align__(16) __half g_bh[(size_t)N_ * F_];   // permuted rows
__device__ float g_posD[(size_t)N_ * PMAX];   // D[perm_i][rank_j] for positives
__device__ float g_negsum[N_];                // permuted space
__device__ float g_a2[N_], g_b2[N_];          // permuted space
__device__ int   g_meta[N_];                  // (cls<<16)|rank per permuted index
__device__ int   g_permpos[N_];               // original row -> permuted position
__device__ int   g_cnt[16];
__device__ int   g_start[16];
__device__ double g_partial[64];
__device__ int   g_done;

// ---------------- helpers ----------------
__device__ __forceinline__ uint32_t smem_u32(const void* p) {
    uint32_t r;
    asm("{ .reg .u64 t; cvta.to.shared.u64 t, %1; cvt.u32.u64 %0, t; }" : "=r"(r) : "l"(p));
    return r;
}
__device__ __forceinline__ float fsqrt_ap(float x) {
    float r; asm("sqrt.approx.f32 %0, %1;" : "=f"(r) : "f"(x)); return r;
}

#define LDSM4(r, addr) \
    asm volatile("ldmatrix.sync.aligned.m8n8.x4.shared.b16 {%0,%1,%2,%3}, [%4];" \
                 : "=r"((r)[0]), "=r"((r)[1]), "=r"((r)[2]), "=r"((r)[3]) : "r"(addr))

#define MMA16816H(d, a, b0, b1) \
    asm volatile("mma.sync.aligned.m16n8k16.row.col.f16.f16.f16.f16 " \
                 "{%0,%1}, {%2,%3,%4,%5}, {%6,%7}, {%0,%1};" \
                 : "+r"((d)[0]), "+r"((d)[1]) \
                 : "r"((a)[0]), "r"((a)[1]), "r"((a)[2]), "r"((a)[3]), "r"(b0), "r"(b1))

#define CP_ASYNC16(saddr, gptr) \
    asm volatile("cp.async.cg.shared.global [%0], [%1], 16;" :: "r"(saddr), "l"(gptr))
#define CP_COMMIT() asm volatile("cp.async.commit_group;" ::: "memory")
#define CP_WAIT1()  asm volatile("cp.async.wait_group 1;" ::: "memory")
#define CP_WAIT0()  asm volatile("cp.async.wait_group 0;" ::: "memory")

// ---------------- perm: class-sort permutation, meta, counts (1 block) ----------------
__global__ void perm_kernel(const int* __restrict__ labels) {
    __shared__ int sc[16], sstart[16];
    int tid = threadIdx.x;
    if (tid < 16) sc[tid] = 0;
    if (tid < 64) g_partial[tid] = 0.0;
    if (tid == 0) g_done = 0;
    __syncthreads();
    for (int e = tid; e < N_; e += blockDim.x) atomicAdd(&sc[labels[e]], 1);
    __syncthreads();
    if (tid == 0) {
        int acc = 0;
        for (int c = 0; c < 16; ++c) { sstart[c] = acc; g_start[c] = acc;
                                       g_cnt[c] = sc[c]; acc += sc[c]; }
    }
    __syncthreads();
    if (tid < 16) sc[tid] = 0;
    __syncthreads();
    for (int e = tid; e < N_; e += blockDim.x) {
        int c = labels[e];
        int r = atomicAdd(&sc[c], 1);
        int pos = sstart[c] + r;
        g_permpos[e] = pos;
        g_meta[pos] = (c << 16) | r;
    }
}

// ---------------- prep: 4 rows per 256-thr block, 2 float4s/thread ----------------
__global__ __launch_bounds__(256)
void prep_kernel(const float* __restrict__ a, const float* __restrict__ b) {
    int q = blockIdx.x & 1023;
    bool isA = blockIdx.x < 1024;
    int r0 = q * 4;
    const float* src = isA ? a : b;
    __half* dsth = isA ? g_ah : g_bh;
    int tid = threadIdx.x;
    int lane = tid & 31, w = tid >> 5;

    int rowA = tid >> 7;            // 0..1
    int rowB = 2 + rowA;            // 2..3
    int elem = tid & 127;
    const float4* s4 = (const float4*)(src + (size_t)r0 * F_);
    float4 v0 = s4[rowA * 128 + elem];
    float4 v1 = s4[rowB * 128 + elem];
    int pA = g_permpos[r0 + rowA];
    int pB = g_permpos[r0 + rowB];

    unsigned short h0, h1, h2, h3;
    h0 = __half_as_ushort(__float2half(v0.x)); h1 = __half_as_ushort(__float2half(v0.y));
    h2 = __half_as_ushort(__float2half(v0.z)); h3 = __half_as_ushort(__float2half(v0.w));
    ((uint2*)dsth)[pA * (F_ / 4) + elem] =
        make_uint2(((uint32_t)h1 << 16) | h0, ((uint32_t)h3 << 16) | h2);
    h0 = __half_as_ushort(__float2half(v1.x)); h1 = __half_as_ushort(__float2half(v1.y));
    h2 = __half_as_ushort(__float2half(v1.z)); h3 = __half_as_ushort(__float2half(v1.w));
    ((uint2*)dsth)[pB * (F_ / 4) + elem] =
        make_uint2(((uint32_t)h1 << 16) | h0, ((uint32_t)h3 << 16) | h2);

    float s0 = v0.x * v0.x + v0.y * v0.y + v0.z * v0.z + v0.w * v0.w;
    float s1 = v1.x * v1.x + v1.y * v1.y + v1.z * v1.z + v1.w * v1.w;
#pragma unroll
    for (int o = 16; o; o >>= 1) {
        s0 += __shfl_xor_sync(0xffffffffu, s0, o);
        s1 += __shfl_xor_sync(0xffffffffu, s1, o);
    }
    __shared__ float ws[16];
    if (lane == 0) { ws[w] = s0; ws[8 + w] = s1; }
    __syncthreads();
    if (tid < 4) {
        float t = ws[tid * 4] + ws[tid * 4 + 1] + ws[tid * 4 + 2] + ws[tid * 4 + 3];
        int pos = g_permpos[r0 + tid];
        if (isA) { g_a2[pos] = t; g_negsum[pos] = 0.0f; }
        else g_b2[pos] = t;
    }
}

// ---------------- dist kernel ----------------
__device__ __forceinline__ void load_stage(uint32_t sb, uint32_t koff,
                                           const char* baseB, const char* baseA,
                                           const uint32_t* goff, const uint32_t* smoff) {
#pragma unroll
    for (int k = 0; k < 4; ++k) CP_ASYNC16(sb + smoff[k], baseB + goff[k] + koff);
#pragma unroll
    for (int k = 4; k < 8; ++k) CP_ASYNC16(sb + smoff[k], baseA + goff[k] + koff);
}

__global__ __launch_bounds__(256, 2)
void dist_kernel() {
    extern __shared__ char smem[];
    const uint32_t sbase = smem_u32(smem);
    const int tid = threadIdx.x;
    const int wid = tid >> 5;
    const int lane = tid & 31;
    const int bi0 = blockIdx.y * TM;
    const int aj0 = blockIdx.x * TNJ;
    const int wm = (wid & 1) * 64;
    const int wn = (wid >> 1) * 32;

    uint32_t goff[8], smoff[8];
#pragma unroll
    for (int t = 0; t < 2; ++t)
#pragma unroll
        for (int q = 0; q < 4; ++q) {
            int linear = tid * 4 + q;
            int r = linear >> 3, cch = linear & 7;
            int row = (t ? aj0 : bi0) + r;
            goff[t * 4 + q] = (uint32_t)(row * (F_ * 2) + cch * 16);
            smoff[t * 4 + q] = (uint32_t)(t * TILE_BYTES + r * 128 + ((cch ^ (r & 7)) << 4));
        }
    const char* baseB = (const char*)g_bh;
    const char* baseA = (const char*)g_ah;

    uint32_t acc[4][4][2];
#pragma unroll
    for (int am = 0; am < 4; ++am)
#pragma unroll
        for (int an = 0; an < 4; ++an) { acc[am][an][0] = 0u; acc[am][an][1] = 0u; }

    load_stage(sbase, 0, baseB, baseA, goff, smoff);                 CP_COMMIT();
    load_stage(sbase + STAGE_BYTES, 128, baseB, baseA, goff, smoff); CP_COMMIT();

    const int lr = lane & 15;
    const int lh = lane >> 4;

#pragma unroll
    for (int c = 0; c < NCH; ++c) {
        if (c < NCH - 1) { CP_WAIT1(); } else { CP_WAIT0(); }
        __syncthreads();
        if (c + 2 < NCH) {
            load_stage(sbase + (uint32_t)((c + 2) % 3) * STAGE_BYTES,
                       (uint32_t)(c + 2) * 128, baseB, baseA, goff, smoff);
            CP_COMMIT();
        }
        uint32_t sb = sbase + (uint32_t)(c % 3) * STAGE_BYTES;

#pragma unroll
        for (int ks = 0; ks < 4; ++ks) {
            uint32_t abh[4][4], bah[2][4];
#pragma unroll
            for (int am = 0; am < 4; ++am) {
                int row = wm + am * 16 + lr;
                uint32_t off = (uint32_t)(row * 128) +
                               (((uint32_t)((ks * 2 + lh) ^ (row & 7))) << 4);
                LDSM4(abh[am], sb + off);
            }
#pragma unroll
            for (int np = 0; np < 2; ++np) {
                int row = wn + np * 16 + lr;
                uint32_t off = (uint32_t)(row * 128) +
                               (((uint32_t)((ks * 2 + lh) ^ (row & 7))) << 4);
                LDSM4(bah[np], sb + TILE_BYTES + off);
            }
#pragma unroll
            for (int am = 0; am < 4; ++am)
#pragma unroll
                for (int an = 0; an < 4; ++an) {
                    uint32_t h0 = bah[an >> 1][an & 1], h1 = bah[an >> 1][(an & 1) + 2];
                    MMA16816H(acc[am][an], abh[am], h0, h1);
                }
        }
    }

    // ------- epilogue: masked negsum + contiguous-window positive store -------
    const int lrow2 = lane >> 2;
    const int lcol = (lane & 3) * 2;
    const int colbase = aj0 + wn + lcol;

    float a2c[4][2];
    int cm[4][2];
#pragma unroll
    for (int an = 0; an < 4; ++an) {
        int gj = colbase + an * 8;
        a2c[an][0] = g_a2[gj];   a2c[an][1] = g_a2[gj + 1];
        cm[an][0] = g_meta[gj];  cm[an][1] = g_meta[gj + 1];
    }

#pragma unroll
    for (int am = 0; am < 4; ++am) {
        int r0 = bi0 + wm + am * 16 + lrow2;
        int r1 = r0 + 8;
        float b20 = g_b2[r0], b21 = g_b2[r1];
        int cl0 = g_meta[r0] >> 16, cl1 = g_meta[r1] >> 16;
        float* p0 = g_posD + (size_t)r0 * PMAX;
        float* p1 = g_posD + (size_t)r1 * PMAX;
        float n0 = 0.0f, n1 = 0.0f;
#pragma unroll
        for (int an = 0; an < 4; ++an) {
            __half2 h0 = *reinterpret_cast<__half2*>(&acc[am][an][0]);
            __half2 h1 = *reinterpret_cast<__half2*>(&acc[am][an][1]);
            float dot[2][2] = {{__low2float(h0), __high2float(h0)},
                               {__low2float(h1), __high2float(h1)}};
#pragma unroll
            for (int cc = 0; cc < 2; ++cc) {
                int gj = colbase + an * 8 + cc;
                int cls = cm[an][cc] >> 16, rnk = cm[an][cc] & 0xffff;
                float dd0 = fsqrt_ap(fmaxf(b20 + a2c[an][cc] - 2.0f * dot[0][cc], 0.0f));
                if (cls != cl0) n0 += __expf(1.0f - dd0);
                else if (gj != r0) p0[rnk] = dd0;
                float dd1 = fsqrt_ap(fmaxf(b21 + a2c[an][cc] - 2.0f * dot[1][cc], 0.0f));
                if (cls != cl1) n1 += __expf(1.0f - dd1);
                else if (gj != r1) p1[rnk] = dd1;
            }
        }
        n0 += __shfl_xor_sync(0xffffffffu, n0, 1);
        n0 += __shfl_xor_sync(0xffffffffu, n0, 2);
        n1 += __shfl_xor_sync(0xffffffffu, n1, 1);
        n1 += __shfl_xor_sync(0xffffffffu, n1, 2);
        if ((lane & 3) == 0) {
            atomicAdd(&g_negsum[r0], n0);
            atomicAdd(&g_negsum[r1], n1);
        }
    }
}

// ---------------- loss: 16 warps/block, warp per row; ns window staged in smem ----------------
__global__ __launch_bounds__(512)
void loss_kernel(float* __restrict__ out) {
    __shared__ float sns[1024];
    __shared__ int swin[2];        // union window [smin, smax)
    int tid = threadIdx.x;
    int lane = tid & 31;
    int warp = tid >> 5;
    int i0 = blockIdx.x * 16;
    int i = i0 + warp;

    int m = g_meta[i];
    int c = m >> 16, ri = m & 0xffff;
    int s = g_start[c], n = g_cnt[c];

    // union window across the block's 16 rows (first & last row suffice: classes contiguous)
    if (tid == 0) {
        int mf = g_meta[i0];
        int ml = g_meta[i0 + 15];
        int cf = mf >> 16, cl = ml >> 16;
        swin[0] = g_start[cf];
        swin[1] = g_start[cl] + g_cnt[cl];
    }
    __syncthreads();
    int smin = swin[0], smax = swin[1];
    for (int t = tid; t < smax - smin; t += 512) sns[t] = g_negsum[smin + t];
    __syncthreads();

    float nsi = g_negsum[i];
    const float* pD = g_posD + (size_t)i * PMAX;
    const float* ns = sns + (s - smin);
    float acc = 0.0f;
    int t = lane;
    for (; t + 96 < n; t += 128) {
        float p0 = pD[t], p1 = pD[t + 32], p2 = pD[t + 64], p3 = pD[t + 96];
        float s0 = ns[t], s1 = ns[t + 32], s2 = ns[t + 64], s3 = ns[t + 96];
        if (t != ri)      { float J = __logf(nsi + s0) + p0; float h = fmaxf(J, 0.0f); acc += h * h; }
        if (t + 32 != ri) { float J = __logf(nsi + s1) + p1; float h = fmaxf(J, 0.0f); acc += h * h; }
        if (t + 64 != ri) { float J = __logf(nsi + s2) + p2; float h = fmaxf(J, 0.0f); acc += h * h; }
        if (t + 96 != ri) { float J = __logf(nsi + s3) + p3; float h = fmaxf(J, 0.0f); acc += h * h; }
    }
    for (; t < n; t += 32) {
        if (t == ri) continue;
        float J = __logf(nsi + ns[t]) + pD[t];
        float h = fmaxf(J, 0.0f);
        acc += h * h;
    }
#pragma unroll
    for (int o = 16; o; o >>= 1) acc += __shfl_xor_sync(0xffffffffu, acc, o);
    __shared__ float fs[16];
    if (lane == 0) fs[warp] = acc;
    __syncthreads();
    if (tid == 0) {
        float tt = 0.0f;
#pragma unroll
        for (int k = 0; k < 16; ++k) tt += fs[k];
        atomicAdd(&g_partial[blockIdx.x & 63], (double)tt);
        __threadfence();
        if (atomicAdd(&g_done, 1) == 255) {
            double tot = 0.0;
            for (int k = 0; k < 64; ++k) tot += g_partial[k];
            long long np = 0;
            for (int k = 0; k < 16; ++k) { long long nn = g_cnt[k]; np += nn * (nn - 1); }
            out[0] = (float)(tot / (2.0 * (double)np));
        }
    }
}

extern "C" void kernel_launch(void* const* d_in, const int* in_sizes, int n_in,
                              void* d_out, int out_size) {
    const float* a = (const float*)d_in[0];
    const float* b = (const float*)d_in[1];
    const int* labels = (const int*)d_in[2];
    float* out = (float*)d_out;

    cudaFuncSetAttribute(dist_kernel, cudaFuncAttributeMaxDynamicSharedMemorySize, SMEM_TOTAL);

    perm_kernel<<<1, 1024>>>(labels);
    prep_kernel<<<2048, 256>>>(a, b);
    dim3 grid(N_ / TNJ, N_ / TM);
    dist_kernel<<<grid, 256, SMEM_TOTAL>>>();
    loss_kernel<<<256, 512>>>(out);
}

// round 16
// speedup vs baseline: 1.0053x; 1.0053x over previous
#include <cuda_runtime.h>
#include <cuda_fp16.h>
#include <cstdint>
#include <math.h>

#define N_ 4096
#define F_ 512
#define TM 128
#define TNJ 128
#define BK 64
#define NCH (F_ / BK)            // 8 k-chunks
#define TILE_BYTES 16384         // 128 rows x 128B
#define STAGE_BYTES (2 * TILE_BYTES)   // 32KB
#define SMEM_TOTAL (3 * STAGE_BYTES)   // 98304, 2 CTAs/SM
#define PMAX 512                 // slots per row (max class size ~306)

// ---------------- scratch ----------------
__device__ __align__(16) __half g_ah[(size_t)N_ * F_];   // permuted rows
__device__ __align__(16) __half g_bh[(size_t)N_ * F_];   // permuted rows
__device__ float g_posD[(size_t)N_ * PMAX];   // D[perm_i][rank_j] for positives
__device__ float g_negsum[N_];                // permuted space
__device__ float g_a2[N_], g_b2[N_];          // permuted space
__device__ int   g_meta[N_];                  // (cls<<16)|rank per permuted index
__device__ int   g_permpos[N_];               // original row -> permuted position
__device__ int   g_cnt[16];
__device__ int   g_start[16];
__device__ double g_partial[64];
__device__ int   g_done;

// ---------------- helpers ----------------
__device__ __forceinline__ uint32_t smem_u32(const void* p) {
    uint32_t r;
    asm("{ .reg .u64 t; cvta.to.shared.u64 t, %1; cvt.u32.u64 %0, t; }" : "=r"(r) : "l"(p));
    return r;
}
__device__ __forceinline__ float fsqrt_ap(float x) {
    float r; asm("sqrt.approx.f32 %0, %1;" : "=f"(r) : "f"(x)); return r;
}

#define LDSM4(r, addr) \
    asm volatile("ldmatrix.sync.aligned.m8n8.x4.shared.b16 {%0,%1,%2,%3}, [%4];" \
                 : "=r"((r)[0]), "=r"((r)[1]), "=r"((r)[2]), "=r"((r)[3]) : "r"(addr))

#define MMA16816H(d, a, b0, b1) \
    asm volatile("mma.sync.aligned.m16n8k16.row.col.f16.f16.f16.f16 " \
                 "{%0,%1}, {%2,%3,%4,%5}, {%6,%7}, {%0,%1};" \
                 : "+r"((d)[0]), "+r"((d)[1]) \
                 : "r"((a)[0]), "r"((a)[1]), "r"((a)[2]), "r"((a)[3]), "r"(b0), "r"(b1))

#define CP_ASYNC16(saddr, gptr) \
    asm volatile("cp.async.cg.shared.global [%0], [%1], 16;" :: "r"(saddr), "l"(gptr))
#define CP_COMMIT() asm volatile("cp.async.commit_group;" ::: "memory")
#define CP_WAIT1()  asm volatile("cp.async.wait_group 1;" ::: "memory")
#define CP_WAIT0()  asm volatile("cp.async.wait_group 0;" ::: "memory")

// ---------------- perm: class-sort permutation, meta, counts (1 block) ----------------
__global__ void perm_kernel(const int* __restrict__ labels) {
    __shared__ int sc[16], sstart[16];
    int tid = threadIdx.x;
    if (tid < 16) sc[tid] = 0;
    if (tid < 64) g_partial[tid] = 0.0;
    if (tid == 0) g_done = 0;
    __syncthreads();
    for (int e = tid; e < N_; e += blockDim.x) atomicAdd(&sc[labels[e]], 1);
    __syncthreads();
    if (tid == 0) {
        int acc = 0;
        for (int c = 0; c < 16; ++c) { sstart[c] = acc; g_start[c] = acc;
                                       g_cnt[c] = sc[c]; acc += sc[c]; }
    }
    __syncthreads();
    if (tid < 16) sc[tid] = 0;
    __syncthreads();
    for (int e = tid; e < N_; e += blockDim.x) {
        int c = labels[e];
        int r = atomicAdd(&sc[c], 1);
        int pos = sstart[c] + r;
        g_permpos[e] = pos;
        g_meta[pos] = (c << 16) | r;
    }
}

// ---------------- prep: 4 rows per 256-thr block, 2 float4s/thread ----------------
__global__ __launch_bounds__(256)
void prep_kernel(const float* __restrict__ a, const float* __restrict__ b) {
    int q = blockIdx.x & 1023;
    bool isA = blockIdx.x < 1024;
    int r0 = q * 4;
    const float* src = isA ? a : b;
    __half* dsth = isA ? g_ah : g_bh;
    int tid = threadIdx.x;
    int lane = tid & 31, w = tid >> 5;

    int rowA = tid >> 7;            // 0..1
    int rowB = 2 + rowA;            // 2..3
    int elem = tid & 127;
    const float4* s4 = (const float4*)(src + (size_t)r0 * F_);
    float4 v0 = s4[rowA * 128 + elem];
    float4 v1 = s4[rowB * 128 + elem];
    int pA = g_permpos[r0 + rowA];
    int pB = g_permpos[r0 + rowB];

    unsigned short h0, h1, h2, h3;
    h0 = __half_as_ushort(__float2half(v0.x)); h1 = __half_as_ushort(__float2half(v0.y));
    h2 = __half_as_ushort(__float2half(v0.z)); h3 = __half_as_ushort(__float2half(v0.w));
    ((uint2*)dsth)[pA * (F_ / 4) + elem] =
        make_uint2(((uint32_t)h1 << 16) | h0, ((uint32_t)h3 << 16) | h2);
    h0 = __half_as_ushort(__float2half(v1.x)); h1 = __half_as_ushort(__float2half(v1.y));
    h2 = __half_as_ushort(__float2half(v1.z)); h3 = __half_as_ushort(__float2half(v1.w));
    ((uint2*)dsth)[pB * (F_ / 4) + elem] =
        make_uint2(((uint32_t)h1 << 16) | h0, ((uint32_t)h3 << 16) | h2);

    float s0 = v0.x * v0.x + v0.y * v0.y + v0.z * v0.z + v0.w * v0.w;
    float s1 = v1.x * v1.x + v1.y * v1.y + v1.z * v1.z + v1.w * v1.w;
#pragma unroll
    for (int o = 16; o; o >>= 1) {
        s0 += __shfl_xor_sync(0xffffffffu, s0, o);
        s1 += __shfl_xor_sync(0xffffffffu, s1, o);
    }
    __shared__ float ws[16];
    if (lane == 0) { ws[w] = s0; ws[8 + w] = s1; }
    __syncthreads();
    if (tid < 4) {
        float t = ws[tid * 4] + ws[tid * 4 + 1] + ws[tid * 4 + 2] + ws[tid * 4 + 3];
        int pos = g_permpos[r0 + tid];
        if (isA) { g_a2[pos] = t; g_negsum[pos] = 0.0f; }
        else g_b2[pos] = t;
    }
}

// ---------------- dist kernel ----------------
__device__ __forceinline__ void load_stage(uint32_t sb, uint32_t koff,
                                           const char* baseB, const char* baseA,
                                           const uint32_t* goff, const uint32_t* smoff) {
#pragma unroll
    for (int k = 0; k < 4; ++k) CP_ASYNC16(sb + smoff[k], baseB + goff[k] + koff);
#pragma unroll
    for (int k = 4; k < 8; ++k) CP_ASYNC16(sb + smoff[k], baseA + goff[k] + koff);
}

__global__ __launch_bounds__(256, 2)
void dist_kernel() {
    extern __shared__ char smem[];
    const uint32_t sbase = smem_u32(smem);
    const int tid = threadIdx.x;
    const int wid = tid >> 5;
    const int lane = tid & 31;
    const int bi0 = blockIdx.y * TM;
    const int aj0 = blockIdx.x * TNJ;
    const int wm = (wid & 1) * 64;
    const int wn = (wid >> 1) * 32;

    uint32_t goff[8], smoff[8];
#pragma unroll
    for (int t = 0; t < 2; ++t)
#pragma unroll
        for (int q = 0; q < 4; ++q) {
            int linear = tid * 4 + q;
            int r = linear >> 3, cch = linear & 7;
            int row = (t ? aj0 : bi0) + r;
            goff[t * 4 + q] = (uint32_t)(row * (F_ * 2) + cch * 16);
            smoff[t * 4 + q] = (uint32_t)(t * TILE_BYTES + r * 128 + ((cch ^ (r & 7)) << 4));
        }
    const char* baseB = (const char*)g_bh;
    const char* baseA = (const char*)g_ah;

    uint32_t acc[4][4][2];
#pragma unroll
    for (int am = 0; am < 4; ++am)
#pragma unroll
        for (int an = 0; an < 4; ++an) { acc[am][an][0] = 0u; acc[am][an][1] = 0u; }

    load_stage(sbase, 0, baseB, baseA, goff, smoff);                 CP_COMMIT();
    load_stage(sbase + STAGE_BYTES, 128, baseB, baseA, goff, smoff); CP_COMMIT();

    const int lr = lane & 15;
    const int lh = lane >> 4;

#pragma unroll
    for (int c = 0; c < NCH; ++c) {
        if (c < NCH - 1) { CP_WAIT1(); } else { CP_WAIT0(); }
        __syncthreads();
        if (c + 2 < NCH) {
            load_stage(sbase + (uint32_t)((c + 2) % 3) * STAGE_BYTES,
                       (uint32_t)(c + 2) * 128, baseB, baseA, goff, smoff);
            CP_COMMIT();
        }
        uint32_t sb = sbase + (uint32_t)(c % 3) * STAGE_BYTES;

#pragma unroll
        for (int ks = 0; ks < 4; ++ks) {
            uint32_t abh[4][4], bah[2][4];
#pragma unroll
            for (int am = 0; am < 4; ++am) {
                int row = wm + am * 16 + lr;
                uint32_t off = (uint32_t)(row * 128) +
                               (((uint32_t)((ks * 2 + lh) ^ (row & 7))) << 4);
                LDSM4(abh[am], sb + off);
            }
#pragma unroll
            for (int np = 0; np < 2; ++np) {
                int row = wn + np * 16 + lr;
                uint32_t off = (uint32_t)(row * 128) +
                               (((uint32_t)((ks * 2 + lh) ^ (row & 7))) << 4);
                LDSM4(bah[np], sb + TILE_BYTES + off);
            }
#pragma unroll
            for (int am = 0; am < 4; ++am)
#pragma unroll
                for (int an = 0; an < 4; ++an) {
                    uint32_t h0 = bah[an >> 1][an & 1], h1 = bah[an >> 1][(an & 1) + 2];
                    MMA16816H(acc[am][an], abh[am], h0, h1);
                }
        }
    }

    // ------- epilogue: masked negsum + contiguous-window positive store -------
    const int lrow2 = lane >> 2;
    const int lcol = (lane & 3) * 2;
    const int colbase = aj0 + wn + lcol;

    float a2c[4][2];
    int cm[4][2];
#pragma unroll
    for (int an = 0; an < 4; ++an) {
        int gj = colbase + an * 8;
        a2c[an][0] = g_a2[gj];   a2c[an][1] = g_a2[gj + 1];
        cm[an][0] = g_meta[gj];  cm[an][1] = g_meta[gj + 1];
    }

#pragma unroll
    for (int am = 0; am < 4; ++am) {
        int r0 = bi0 + wm + am * 16 + lrow2;
        int r1 = r0 + 8;
        float b20 = g_b2[r0], b21 = g_b2[r1];
        int cl0 = g_meta[r0] >> 16, cl1 = g_meta[r1] >> 16;
        float* p0 = g_posD + (size_t)r0 * PMAX;
        float* p1 = g_posD + (size_t)r1 * PMAX;
        float n0 = 0.0f, n1 = 0.0f;
#pragma unroll
        for (int an = 0; an < 4; ++an) {
            __half2 h0 = *reinterpret_cast<__half2*>(&acc[am][an][0]);
            __half2 h1 = *reinterpret_cast<__half2*>(&acc[am][an][1]);
            float dot[2][2] = {{__low2float(h0), __high2float(h0)},
                               {__low2float(h1), __high2float(h1)}};
#pragma unroll
            for (int cc = 0; cc < 2; ++cc) {
                int gj = colbase + an * 8 + cc;
                int cls = cm[an][cc] >> 16, rnk = cm[an][cc] & 0xffff;
                float dd0 = fsqrt_ap(fmaxf(b20 + a2c[an][cc] - 2.0f * dot[0][cc], 0.0f));
                if (cls != cl0) n0 += __expf(1.0f - dd0);
                else if (gj != r0) p0[rnk] = dd0;
                float dd1 = fsqrt_ap(fmaxf(b21 + a2c[an][cc] - 2.0f * dot[1][cc], 0.0f));
                if (cls != cl1) n1 += __expf(1.0f - dd1);
                else if (gj != r1) p1[rnk] = dd1;
            }
        }
        n0 += __shfl_xor_sync(0xffffffffu, n0, 1);
        n0 += __shfl_xor_sync(0xffffffffu, n0, 2);
        n1 += __shfl_xor_sync(0xffffffffu, n1, 1);
        n1 += __shfl_xor_sync(0xffffffffu, n1, 2);
        if ((lane & 3) == 0) {
            atomicAdd(&g_negsum[r0], n0);
            atomicAdd(&g_negsum[r1], n1);
        }
    }
}

// ---------------- loss: 16 warps/block, warp per row, 2-way ILP (R12 shape); last block finalizes ----------------
__global__ __launch_bounds__(512)
void loss_kernel(float* __restrict__ out) {
    int lane = threadIdx.x & 31;
    int warp = threadIdx.x >> 5;
    int i = blockIdx.x * 16 + warp;
    int m = g_meta[i];
    int c = m >> 16, ri = m & 0xffff;
    int s = g_start[c], n = g_cnt[c];
    float nsi = g_negsum[i];
    const float* pD = g_posD + (size_t)i * PMAX;
    const float* ns = g_negsum + s;
    float acc = 0.0f;
    int t = lane;
    for (; t + 32 < n; t += 64) {
        float pa = pD[t], nsa = ns[t];
        float pb = pD[t + 32], nsb = ns[t + 32];
        if (t != ri) {
            float J = __logf(nsi + nsa) + pa;
            float h = fmaxf(J, 0.0f);
            acc += h * h;
        }
        if (t + 32 != ri) {
            float J = __logf(nsi + nsb) + pb;
            float h = fmaxf(J, 0.0f);
            acc += h * h;
        }
    }
    if (t < n && t != ri) {
        float J = __logf(nsi + ns[t]) + pD[t];
        float h = fmaxf(J, 0.0f);
        acc += h * h;
    }
#pragma unroll
    for (int o = 16; o; o >>= 1) acc += __shfl_xor_sync(0xffffffffu, acc, o);
    __shared__ float fs[16];
    if (lane == 0) fs[warp] = acc;
    __syncthreads();
    if (threadIdx.x == 0) {
        float tt = 0.0f;
#pragma unroll
        for (int k = 0; k < 16; ++k) tt += fs[k];
        atomicAdd(&g_partial[blockIdx.x & 63], (double)tt);
        __threadfence();
        if (atomicAdd(&g_done, 1) == 255) {
            double tot = 0.0;
            for (int k = 0; k < 64; ++k) tot += g_partial[k];
            long long np = 0;
            for (int k = 0; k < 16; ++k) { long long nn = g_cnt[k]; np += nn * (nn - 1); }
            out[0] = (float)(tot / (2.0 * (double)np));
        }
    }
}

extern "C" void kernel_launch(void* const* d_in, const int* in_sizes, int n_in,
                              void* d_out, int out_size) {
    const float* a = (const float*)d_in[0];
    const float* b = (const float*)d_in[1];
    const int* labels = (const int*)d_in[2];
    float* out = (float*)d_out;

    cudaFuncSetAttribute(dist_kernel, cudaFuncAttributeMaxDynamicSharedMemorySize, SMEM_TOTAL);

    perm_kernel<<<1, 1024>>>(labels);
    prep_kernel<<<2048, 256>>>(a, b);
    dim3 grid(N_ / TNJ, N_ / TM);
    dist_kernel<<<grid, 256, SMEM_TOTAL>>>();
    loss_kernel<<<256, 512>>>(out);
}

// round 17
// speedup vs baseline: 1.0224x; 1.0170x over previous
#include <cuda_runtime.h>
#include <cuda_fp16.h>
#include <cstdint>
#include <math.h>

#define N_ 4096
#define F_ 512                   // bytes per row in fp8 (= elements)
#define TM 128
#define TNJ 128
#define NCH 4                    // 4 k-chunks of 128 fp8 elements
#define TILE_BYTES 16384         // 128 rows x 128B
#define STAGE_BYTES (2 * TILE_BYTES)   // 32KB
#define SMEM_TOTAL (3 * STAGE_BYTES)   // 98304, 2 CTAs/SM
#define PMAX 512                 // slots per row (max class size ~306)

// ---------------- scratch ----------------
__device__ __align__(16) unsigned char g_a8[(size_t)N_ * F_];   // permuted rows, e4m3
__device__ __align__(16) unsigned char g_b8[(size_t)N_ * F_];   // permuted rows, e4m3
__device__ float g_posD[(size_t)N_ * PMAX];   // D[perm_i][rank_j] for positives
__device__ float g_negsum[N_];                // permuted space
__device__ float g_a2[N_], g_b2[N_];          // permuted space
__device__ int   g_meta[N_];                  // (cls<<16)|rank per permuted index
__device__ int   g_permpos[N_];               // original row -> permuted position
__device__ int   g_cnt[16];
__device__ int   g_start[16];
__device__ double g_partial[64];
__device__ int   g_done;

// ---------------- helpers ----------------
__device__ __forceinline__ uint32_t smem_u32(const void* p) {
    uint32_t r;
    asm("{ .reg .u64 t; cvta.to.shared.u64 t, %1; cvt.u32.u64 %0, t; }" : "=r"(r) : "l"(p));
    return r;
}
__device__ __forceinline__ float fsqrt_ap(float x) {
    float r; asm("sqrt.approx.f32 %0, %1;" : "=f"(r) : "f"(x)); return r;
}
__device__ __forceinline__ uint32_t f4_to_e4m3x4(float4 v) {
    unsigned short lo, hi;
    asm("cvt.rn.satfinite.e4m3x2.f32 %0, %1, %2;" : "=h"(lo) : "f"(v.y), "f"(v.x));
    asm("cvt.rn.satfinite.e4m3x2.f32 %0, %1, %2;" : "=h"(hi) : "f"(v.w), "f"(v.z));
    return (uint32_t)lo | ((uint32_t)hi << 16);
}

#define LDSM4(r, addr) \
    asm volatile("ldmatrix.sync.aligned.m8n8.x4.shared.b16 {%0,%1,%2,%3}, [%4];" \
                 : "=r"((r)[0]), "=r"((r)[1]), "=r"((r)[2]), "=r"((r)[3]) : "r"(addr))

// fp8 e4m3 MMA, K=32 per instruction, fp32 accumulate
#define MMAF8(d, a, b0, b1) \
    asm volatile("mma.sync.aligned.m16n8k32.row.col.f32.e4m3.e4m3.f32 " \
                 "{%0,%1,%2,%3}, {%4,%5,%6,%7}, {%8,%9}, {%0,%1,%2,%3};" \
                 : "+f"((d)[0]), "+f"((d)[1]), "+f"((d)[2]), "+f"((d)[3]) \
                 : "r"((a)[0]), "r"((a)[1]), "r"((a)[2]), "r"((a)[3]), "r"(b0), "r"(b1))

#define CP_ASYNC16(saddr, gptr) \
    asm volatile("cp.async.cg.shared.global [%0], [%1], 16;" :: "r"(saddr), "l"(gptr))
#define CP_COMMIT() asm volatile("cp.async.commit_group;" ::: "memory")
#define CP_WAIT1()  asm volatile("cp.async.wait_group 1;" ::: "memory")
#define CP_WAIT0()  asm volatile("cp.async.wait_group 0;" ::: "memory")

// ---------------- perm: class-sort permutation, meta, counts (1 block) ----------------
__global__ void perm_kernel(const int* __restrict__ labels) {
    __shared__ int sc[16], sstart[16];
    int tid = threadIdx.x;
    if (tid < 16) sc[tid] = 0;
    if (tid < 64) g_partial[tid] = 0.0;
    if (tid == 0) g_done = 0;
    __syncthreads();
    for (int e = tid; e < N_; e += blockDim.x) atomicAdd(&sc[labels[e]], 1);
    __syncthreads();
    if (tid == 0) {
        int acc = 0;
        for (int c = 0; c < 16; ++c) { sstart[c] = acc; g_start[c] = acc;
                                       g_cnt[c] = sc[c]; acc += sc[c]; }
    }
    __syncthreads();
    if (tid < 16) sc[tid] = 0;
    __syncthreads();
    for (int e = tid; e < N_; e += blockDim.x) {
        int c = labels[e];
        int r = atomicAdd(&sc[c], 1);
        int pos = sstart[c] + r;
        g_permpos[e] = pos;
        g_meta[pos] = (c << 16) | r;
    }
}

// ---------------- prep: 4 rows per 256-thr block, 2 float4s/thread; fp8 convert ----------------
__global__ __launch_bounds__(256)
void prep_kernel(const float* __restrict__ a, const float* __restrict__ b) {
    int q = blockIdx.x & 1023;
    bool isA = blockIdx.x < 1024;
    int r0 = q * 4;
    const float* src = isA ? a : b;
    uint32_t* dst8 = (uint32_t*)(isA ? g_a8 : g_b8);
    int tid = threadIdx.x;
    int lane = tid & 31, w = tid >> 5;

    int rowA = tid >> 7;            // 0..1
    int rowB = 2 + rowA;            // 2..3
    int elem = tid & 127;
    const float4* s4 = (const float4*)(src + (size_t)r0 * F_);
    float4 v0 = s4[rowA * 128 + elem];
    float4 v1 = s4[rowB * 128 + elem];
    int pA = g_permpos[r0 + rowA];
    int pB = g_permpos[r0 + rowB];

    dst8[pA * (F_ / 4) + elem] = f4_to_e4m3x4(v0);
    dst8[pB * (F_ / 4) + elem] = f4_to_e4m3x4(v1);

    float s0 = v0.x * v0.x + v0.y * v0.y + v0.z * v0.z + v0.w * v0.w;
    float s1 = v1.x * v1.x + v1.y * v1.y + v1.z * v1.z + v1.w * v1.w;
#pragma unroll
    for (int o = 16; o; o >>= 1) {
        s0 += __shfl_xor_sync(0xffffffffu, s0, o);
        s1 += __shfl_xor_sync(0xffffffffu, s1, o);
    }
    __shared__ float ws[16];
    if (lane == 0) { ws[w] = s0; ws[8 + w] = s1; }
    __syncthreads();
    if (tid < 4) {
        float t = ws[tid * 4] + ws[tid * 4 + 1] + ws[tid * 4 + 2] + ws[tid * 4 + 3];
        int pos = g_permpos[r0 + tid];
        if (isA) { g_a2[pos] = t; g_negsum[pos] = 0.0f; }
        else g_b2[pos] = t;
    }
}

// ---------------- dist kernel: fp8 k32 HMMA ----------------
__device__ __forceinline__ void load_stage(uint32_t sb, uint32_t koff,
                                           const char* baseB, const char* baseA,
                                           const uint32_t* goff, const uint32_t* smoff) {
#pragma unroll
    for (int k = 0; k < 4; ++k) CP_ASYNC16(sb + smoff[k], baseB + goff[k] + koff);
#pragma unroll
    for (int k = 4; k < 8; ++k) CP_ASYNC16(sb + smoff[k], baseA + goff[k] + koff);
}

__global__ __launch_bounds__(256, 2)
void dist_kernel() {
    extern __shared__ char smem[];
    const uint32_t sbase = smem_u32(smem);
    const int tid = threadIdx.x;
    const int wid = tid >> 5;
    const int lane = tid & 31;
    const int bi0 = blockIdx.y * TM;
    const int aj0 = blockIdx.x * TNJ;
    const int wm = (wid & 1) * 64;
    const int wn = (wid >> 1) * 32;

    // hoisted addressing: tile row = 128 B (chunk of K), global row = 512 B
    uint32_t goff[8], smoff[8];
#pragma unroll
    for (int t = 0; t < 2; ++t)
#pragma unroll
        for (int q = 0; q < 4; ++q) {
            int linear = tid * 4 + q;
            int r = linear >> 3, cch = linear & 7;
            int row = (t ? aj0 : bi0) + r;
            goff[t * 4 + q] = (uint32_t)(row * F_ + cch * 16);
            smoff[t * 4 + q] = (uint32_t)(t * TILE_BYTES + r * 128 + ((cch ^ (r & 7)) << 4));
        }
    const char* baseB = (const char*)g_b8;
    const char* baseA = (const char*)g_a8;

    float acc[4][4][4];
#pragma unroll
    for (int am = 0; am < 4; ++am)
#pragma unroll
        for (int an = 0; an < 4; ++an)
#pragma unroll
            for (int x = 0; x < 4; ++x) acc[am][an][x] = 0.0f;

    load_stage(sbase, 0, baseB, baseA, goff, smoff);                 CP_COMMIT();
    load_stage(sbase + STAGE_BYTES, 128, baseB, baseA, goff, smoff); CP_COMMIT();

    const int lr = lane & 15;
    const int lh = lane >> 4;

#pragma unroll
    for (int c = 0; c < NCH; ++c) {
        if (c < NCH - 1) { CP_WAIT1(); } else { CP_WAIT0(); }
        __syncthreads();
        if (c + 2 < NCH) {
            load_stage(sbase + (uint32_t)((c + 2) % 3) * STAGE_BYTES,
                       (uint32_t)(c + 2) * 128, baseB, baseA, goff, smoff);
            CP_COMMIT();
        }
        uint32_t sb = sbase + (uint32_t)(c % 3) * STAGE_BYTES;

        // k-slice = 32 fp8 bytes; 4 slices per 128B chunk
#pragma unroll
        for (int ks = 0; ks < 4; ++ks) {
            uint32_t abh[4][4], bah[2][4];
#pragma unroll
            for (int am = 0; am < 4; ++am) {
                int row = wm + am * 16 + lr;
                uint32_t off = (uint32_t)(row * 128) +
                               (((uint32_t)((ks * 2 + lh) ^ (row & 7))) << 4);
                LDSM4(abh[am], sb + off);
            }
#pragma unroll
            for (int np = 0; np < 2; ++np) {
                int row = wn + np * 16 + lr;
                uint32_t off = (uint32_t)(row * 128) +
                               (((uint32_t)((ks * 2 + lh) ^ (row & 7))) << 4);
                LDSM4(bah[np], sb + TILE_BYTES + off);
            }
#pragma unroll
            for (int am = 0; am < 4; ++am)
#pragma unroll
                for (int an = 0; an < 4; ++an) {
                    uint32_t h0 = bah[an >> 1][an & 1], h1 = bah[an >> 1][(an & 1) + 2];
                    MMAF8(acc[am][an], abh[am], h0, h1);
                }
        }
    }

    // ------- epilogue: masked negsum + contiguous-window positive store -------
    const int lrow2 = lane >> 2;
    const int lcol = (lane & 3) * 2;
    const int colbase = aj0 + wn + lcol;

    float a2c[4][2];
    int cm[4][2];
#pragma unroll
    for (int an = 0; an < 4; ++an) {
        int gj = colbase + an * 8;
        a2c[an][0] = g_a2[gj];   a2c[an][1] = g_a2[gj + 1];
        cm[an][0] = g_meta[gj];  cm[an][1] = g_meta[gj + 1];
    }

#pragma unroll
    for (int am = 0; am < 4; ++am) {
        int r0 = bi0 + wm + am * 16 + lrow2;
        int r1 = r0 + 8;
        float b20 = g_b2[r0], b21 = g_b2[r1];
        int cl0 = g_meta[r0] >> 16, cl1 = g_meta[r1] >> 16;
        float* p0 = g_posD + (size_t)r0 * PMAX;
        float* p1 = g_posD + (size_t)r1 * PMAX;
        float n0 = 0.0f, n1 = 0.0f;
#pragma unroll
        for (int an = 0; an < 4; ++an)
#pragma unroll
            for (int cc = 0; cc < 2; ++cc) {
                int gj = colbase + an * 8 + cc;
                int cls = cm[an][cc] >> 16, rnk = cm[an][cc] & 0xffff;
                float dd0 = fsqrt_ap(fmaxf(b20 + a2c[an][cc] - 2.0f * acc[am][an][cc], 0.0f));
                if (cls != cl0) n0 += __expf(1.0f - dd0);
                else if (gj != r0) p0[rnk] = dd0;
                float dd1 = fsqrt_ap(fmaxf(b21 + a2c[an][cc] - 2.0f * acc[am][an][2 + cc], 0.0f));
                if (cls != cl1) n1 += __expf(1.0f - dd1);
                else if (gj != r1) p1[rnk] = dd1;
            }
        n0 += __shfl_xor_sync(0xffffffffu, n0, 1);
        n0 += __shfl_xor_sync(0xffffffffu, n0, 2);
        n1 += __shfl_xor_sync(0xffffffffu, n1, 1);
        n1 += __shfl_xor_sync(0xffffffffu, n1, 2);
        if ((lane & 3) == 0) {
            atomicAdd(&g_negsum[r0], n0);
            atomicAdd(&g_negsum[r1], n1);
        }
    }
}

// ---------------- loss: 16 warps/block, warp per row, 2-way ILP; last block finalizes ----------------
__global__ __launch_bounds__(512)
void loss_kernel(float* __restrict__ out) {
    int lane = threadIdx.x & 31;
    int warp = threadIdx.x >> 5;
    int i = blockIdx.x * 16 + warp;
    int m = g_meta[i];
    int c = m >> 16, ri = m & 0xffff;
    int s = g_start[c], n = g_cnt[c];
    float nsi = g_negsum[i];
    const float* pD = g_posD + (size_t)i * PMAX;
    const float* ns = g_negsum + s;
    float acc = 0.0f;
    int t = lane;
    for (; t + 32 < n; t += 64) {
        float pa = pD[t], nsa = ns[t];
        float pb = pD[t + 32], nsb = ns[t + 32];
        if (t != ri) {
            float J = __logf(nsi + nsa) + pa;
            float h = fmaxf(J, 0.0f);
            acc += h * h;
        }
        if (t + 32 != ri) {
            float J = __logf(nsi + nsb) + pb;
            float h = fmaxf(J, 0.0f);
            acc += h * h;
        }
    }
    if (t < n && t != ri) {
        float J = __logf(nsi + ns[t]) + pD[t];
        float h = fmaxf(J, 0.0f);
        acc += h * h;
    }
#pragma unroll
    for (int o = 16; o; o >>= 1) acc += __shfl_xor_sync(0xffffffffu, acc, o);
    __shared__ float fs[16];
    if (lane == 0) fs[warp] = acc;
    __syncthreads();
    if (threadIdx.x == 0) {
        float tt = 0.0f;
#pragma unroll
        for (int k = 0; k < 16; ++k) tt += fs[k];
        atomicAdd(&g_partial[blockIdx.x & 63], (double)tt);
        __threadfence();
        if (atomicAdd(&g_done, 1) == 255) {
            double tot = 0.0;
            for (int k = 0; k < 64; ++k) tot += g_partial[k];
            long long np = 0;
            for (int k = 0; k < 16; ++k) { long long nn = g_cnt[k]; np += nn * (nn - 1); }
            out[0] = (float)(tot / (2.0 * (double)np));
        }
    }
}

extern "C" void kernel_launch(void* const* d_in, const int* in_sizes, int n_in,
                              void* d_out, int out_size) {
    const float* a = (const float*)d_in[0];
    const float* b = (const float*)d_in[1];
    const int* labels = (const int*)d_in[2];
    float* out = (float*)d_out;

    cudaFuncSetAttribute(dist_kernel, cudaFuncAttributeMaxDynamicSharedMemorySize, SMEM_TOTAL);

    perm_kernel<<<1, 1024>>>(labels);
    prep_kernel<<<2048, 256>>>(a, b);
    dim3 grid(N_ / TNJ, N_ / TM);
    dist_kernel<<<grid, 256, SMEM_TOTAL>>>();
    loss_kernel<<<256, 512>>>(out);
}